// round 2
// baseline (speedup 1.0000x reference)
#include <cuda_runtime.h>
#include <math.h>

#define B 128
#define P 8732
#define O 16
#define C 21
#define NT 256
#define SB 4                       // sub-blocks per image for match kernels
#define PPB (P / SB)               // 2183 priors per sub-block
#define TILES ((P + NT - 1) / NT)  // 35

// ---------------- device scratch (no allocations allowed) ----------------
__device__ unsigned char      g_tc  [B * P];       // tentative conf per prior (pre-force)
__device__ unsigned char      g_bix [B * P];       // best-truth idx per prior
__device__ unsigned char      g_conf[B * P];       // final conf per prior (0 = background)
__device__ unsigned long long g_part[B * SB * O];  // per-subblock per-truth packed argmax
__device__ float              g_negce[B * P];      // CE at negatives, 0 at positives
__device__ int                g_np4 [B * SB];      // npos partials
__device__ float              g_loc4[B * SB];      // smoothL1 partials
__device__ float              g_posce[B * TILES];  // per-tile positive-CE partials
__device__ float              g_negsum[B];         // hard-negative top-K CE sum

__device__ __forceinline__ float sl1f(float x) {
    float ax = fabsf(x);
    return ax < 1.0f ? 0.5f * ax * ax : ax - 0.5f;
}

// ---------------- kernel 1: single-pass IoU -> per-prior best + per-truth partial argmax
__global__ __launch_bounds__(NT)
void k_match1(const float* __restrict__ boxes,
              const int*   __restrict__ labels,
              const float* __restrict__ priors) {
    const int b = blockIdx.y, s = blockIdx.x, tid = threadIdx.x;
    __shared__ float4 s_truth[O];
    __shared__ float  s_area[O];
    __shared__ int    s_label[O];
    __shared__ unsigned long long s_red[O * 8];

    if (tid < O) {
        float4 t = ((const float4*)boxes)[b * O + tid];
        s_truth[tid] = t;
        s_area[tid]  = (t.z - t.x) * (t.w - t.y);
        s_label[tid] = labels[b * O + tid];
    }
    __syncthreads();

    // packed per-truth best: (iou_bits << 32) | (P-1-p). iou>=0 so float bits
    // are order-preserving; inverted index -> max picks smallest p on ties
    // (matches jnp.argmax first-occurrence).
    unsigned long long tb[O];
#pragma unroll
    for (int o = 0; o < O; o++) tb[o] = 0ull;

    const int p0 = s * PPB;
    for (int p = p0 + tid; p < p0 + PPB; p += NT) {
        float4 pr = ((const float4*)priors)[p];
        float px0 = pr.x - 0.5f * pr.z, py0 = pr.y - 0.5f * pr.w;
        float px1 = pr.x + 0.5f * pr.z, py1 = pr.y + 0.5f * pr.w;
        float pa  = pr.z * pr.w;
        float bov = -1.0f; int bix = 0;
#pragma unroll
        for (int o = 0; o < O; o++) {
            float4 t = s_truth[o];
            float ix = fmaxf(fminf(t.z, px1) - fmaxf(t.x, px0), 0.0f);
            float iy = fmaxf(fminf(t.w, py1) - fmaxf(t.y, py0), 0.0f);
            float inter = ix * iy;
            float iou = inter / (s_area[o] + pa - inter);
            if (iou > bov) { bov = iou; bix = o; }     // ascending o: first occurrence
            unsigned long long key =
                ((unsigned long long)__float_as_uint(iou) << 32) |
                (unsigned)(P - 1 - p);
            if (key > tb[o]) tb[o] = key;
        }
        int tc = (bov < 0.5f) ? 0 : (s_label[bix] + 1);
        g_tc [b * P + p] = (unsigned char)tc;
        g_bix[b * P + p] = (unsigned char)bix;
    }

    const int lane = tid & 31, wid = tid >> 5;
#pragma unroll
    for (int o = 0; o < O; o++) {
        unsigned long long v = tb[o];
        for (int sh = 16; sh > 0; sh >>= 1) {
            unsigned long long v2 = __shfl_down_sync(0xffffffffu, v, sh);
            if (v2 > v) v = v2;
        }
        if (lane == 0) s_red[o * 8 + wid] = v;
    }
    __syncthreads();
    if (tid < O) {
        unsigned long long v = s_red[tid * 8];
        for (int w = 1; w < 8; w++) {
            unsigned long long v2 = s_red[tid * 8 + w];
            if (v2 > v) v = v2;
        }
        g_part[(b * SB + s) * O + tid] = v;
    }
}

// ---------------- kernel 2: forced-assign + final conf + loc loss ----------------
__global__ __launch_bounds__(NT)
void k_match2(const float* __restrict__ loc,
              const float* __restrict__ boxes,
              const int*   __restrict__ labels,
              const float* __restrict__ priors) {
    const int b = blockIdx.y, s = blockIdx.x, tid = threadIdx.x;
    __shared__ float4 s_truth[O];
    __shared__ int    s_label[O];
    __shared__ int    s_forced[O];
    __shared__ float  s_rv[8];
    __shared__ int    s_ri[8];

    if (tid < O) {
        s_truth[tid] = ((const float4*)boxes)[b * O + tid];
        s_label[tid] = labels[b * O + tid];
        unsigned long long v = g_part[(b * SB + 0) * O + tid];
        for (int ss = 1; ss < SB; ss++) {
            unsigned long long v2 = g_part[(b * SB + ss) * O + tid];
            if (v2 > v) v = v2;
        }
        s_forced[tid] = P - 1 - (int)(unsigned)(v & 0xffffffffu);
    }
    __syncthreads();

    int npos = 0; float slsum = 0.0f;
    const int p0 = s * PPB;
    for (int p = p0 + tid; p < p0 + PPB; p += NT) {
        int tc  = g_tc [b * P + p];
        int bix = g_bix[b * P + p];
#pragma unroll
        for (int o = 0; o < O; o++)                // ascending: last wins (matches .at.set)
            if (s_forced[o] == p) { bix = o; tc = s_label[o] + 1; }
        g_conf[b * P + p] = (unsigned char)tc;
        if (tc > 0) {
            npos++;
            float4 pr = ((const float4*)priors)[p];
            float4 t  = s_truth[bix];
            float4 lp = ((const float4*)loc)[b * P + p];
            float gx = ((t.x + t.z) * 0.5f - pr.x) / (0.1f * pr.z);
            float gy = ((t.y + t.w) * 0.5f - pr.y) / (0.1f * pr.w);
            float gw = logf((t.z - t.x) / pr.z) / 0.2f;
            float gh = logf((t.w - t.y) / pr.w) / 0.2f;
            slsum += sl1f(lp.x - gx) + sl1f(lp.y - gy)
                   + sl1f(lp.z - gw) + sl1f(lp.w - gh);
        }
    }
    const int lane = tid & 31, wid = tid >> 5;
    float v = slsum; int n = npos;
    for (int sh = 16; sh > 0; sh >>= 1) {
        v += __shfl_down_sync(0xffffffffu, v, sh);
        n += __shfl_down_sync(0xffffffffu, n, sh);
    }
    if (lane == 0) { s_rv[wid] = v; s_ri[wid] = n; }
    __syncthreads();
    if (tid == 0) {
        float tv = 0.0f; int tn = 0;
        for (int w = 0; w < 8; w++) { tv += s_rv[w]; tn += s_ri[w]; }
        g_loc4[b * SB + s] = tv; g_np4[b * SB + s] = tn;
    }
}

// ---------------- kernel 3: per-prior cross entropy ----------------
__global__ __launch_bounds__(NT)
void k_ce(const float* __restrict__ conf) {
    __shared__ float s[NT * C];   // 21504 B
    __shared__ float s_r[8];
    const int b = blockIdx.y, tile = blockIdx.x, tid = threadIdx.x;
    const int p0  = tile * NT;
    const int cnt = min(NT, P - p0);

    // cnt*C divisible by 4 (256*21=5376, 28*21=588); base element offset div by 4.
    const float4* src = (const float4*)(conf + ((size_t)b * P + p0) * C);
    float4* dst = (float4*)s;
    const int n4 = cnt * C / 4;
    for (int i = tid; i < n4; i += NT) dst[i] = src[i];
    __syncthreads();

    float posce = 0.0f;
    if (tid < cnt) {
        const float* x = s + tid * C;   // stride 21: bank-conflict-free
        float m = x[0];
#pragma unroll
        for (int c = 1; c < C; c++) m = fmaxf(m, x[c]);
        float sum = 0.0f;
#pragma unroll
        for (int c = 0; c < C; c++) sum += expf(x[c] - m);
        float lse = m + logf(sum);
        const int p   = p0 + tid;
        const int cls = g_conf[b * P + p];
        float ce = lse - x[cls];
        if (cls > 0) { g_negce[b * P + p] = 0.0f; posce = ce; }
        else         { g_negce[b * P + p] = ce; }
    }
    float v = posce;
    for (int s2 = 16; s2 > 0; s2 >>= 1) v += __shfl_down_sync(0xffffffffu, v, s2);
    if ((tid & 31) == 0) s_r[tid >> 5] = v;
    __syncthreads();
    if (tid == 0) {
        float tv = 0.0f;
        for (int w = 0; w < 8; w++) tv += s_r[w];
        g_posce[b * TILES + tile] = tv;
    }
}

// ---------------- kernel 4: exact top-K sum via radix select in shared ----------------
__global__ __launch_bounds__(NT)
void k_topk() {
    __shared__ float        sv[P];         // 34928 B
    __shared__ unsigned int hist[256];
    __shared__ unsigned int s_sel, s_krem;
    __shared__ float        s_s[8];
    __shared__ unsigned int s_c[8];
    const int b = blockIdx.x, tid = threadIdx.x;

    const float4* src = (const float4*)(g_negce + b * P);
    float4* d4 = (float4*)sv;
    for (int i = tid; i < P / 4; i += NT) d4[i] = src[i];
    int K = 3 * (g_np4[b * SB] + g_np4[b * SB + 1] + g_np4[b * SB + 2] + g_np4[b * SB + 3]);
    if (K > P) K = P;
    __syncthreads();
    if (K <= 0) { if (tid == 0) g_negsum[b] = 0.0f; return; }

    // CE >= 0 => float order == uint order. Find K-th largest bit pattern.
    unsigned prefix = 0, prefmask = 0, Krem = (unsigned)K;
    for (int shift = 24; shift >= 0; shift -= 8) {
        hist[tid] = 0;
        __syncthreads();
        for (int i = tid; i < P; i += NT) {
            unsigned u = __float_as_uint(sv[i]);
            if ((u & prefmask) == prefix) atomicAdd(&hist[(u >> shift) & 255u], 1u);
        }
        __syncthreads();
        if (tid == 0) {
            unsigned run = 0; int bin = 255;
            for (; bin > 0; bin--) {
                unsigned c = hist[bin];
                if (run + c >= Krem) break;
                run += c;
            }
            s_sel  = prefix | ((unsigned)bin << shift);
            s_krem = Krem - run;
        }
        __syncthreads();
        prefix = s_sel; Krem = s_krem;
        prefmask |= 0xFFu << shift;
        __syncthreads();
    }
    const float thr = __uint_as_float(prefix);   // exact K-th largest value
    float ssum = 0.0f; unsigned cgt = 0;
    for (int i = tid; i < P; i += NT) {
        float v = sv[i];
        if (v > thr) { ssum += v; cgt++; }
    }
    for (int s = 16; s > 0; s >>= 1) {
        ssum += __shfl_down_sync(0xffffffffu, ssum, s);
        cgt  += __shfl_down_sync(0xffffffffu, cgt, s);
    }
    if ((tid & 31) == 0) { s_s[tid >> 5] = ssum; s_c[tid >> 5] = cgt; }
    __syncthreads();
    if (tid == 0) {
        float ts = 0.0f; unsigned tc = 0;
        for (int w = 0; w < 8; w++) { ts += s_s[w]; tc += s_c[w]; }
        g_negsum[b] = ts + (float)((unsigned)K - tc) * thr;  // exact tie handling
    }
}

// ---------------- kernel 5: final scalar ----------------
__global__ __launch_bounds__(NT)
void k_final(float* __restrict__ out) {
    __shared__ float s_l[8], s_p[8], s_n[8];
    __shared__ int   s_c[8];
    const int tid = threadIdx.x;
    float locs = 0.0f, poss = 0.0f, negs = 0.0f; int np = 0;
    for (int i = tid; i < B * SB; i += NT) { locs += g_loc4[i]; np += g_np4[i]; }
    for (int b = tid; b < B; b += NT) negs += g_negsum[b];
    for (int i = tid; i < B * TILES; i += NT) poss += g_posce[i];
    for (int s = 16; s > 0; s >>= 1) {
        locs += __shfl_down_sync(0xffffffffu, locs, s);
        poss += __shfl_down_sync(0xffffffffu, poss, s);
        negs += __shfl_down_sync(0xffffffffu, negs, s);
        np   += __shfl_down_sync(0xffffffffu, np, s);
    }
    if ((tid & 31) == 0) {
        int w = tid >> 5;
        s_l[w] = locs; s_p[w] = poss; s_n[w] = negs; s_c[w] = np;
    }
    __syncthreads();
    if (tid == 0) {
        float tl = 0, tp = 0, tn = 0; int tc = 0;
        for (int w = 0; w < 8; w++) { tl += s_l[w]; tp += s_p[w]; tn += s_n[w]; tc += s_c[w]; }
        float npf = (float)tc;
        out[0] = (tn + tp) / (npf + 1e-7f) + tl / (4.0f * npf);
    }
}

// ---------------- launcher ----------------
extern "C" void kernel_launch(void* const* d_in, const int* in_sizes, int n_in,
                              void* d_out, int out_size) {
    (void)in_sizes; (void)n_in; (void)out_size;
    const float* loc    = (const float*)d_in[0];
    const float* conf   = (const float*)d_in[1];
    const float* boxes  = (const float*)d_in[2];
    const int*   labels = (const int*)  d_in[3];
    const float* priors = (const float*)d_in[4];

    dim3 gm(SB, B);
    k_match1<<<gm, NT>>>(boxes, labels, priors);
    k_match2<<<gm, NT>>>(loc, boxes, labels, priors);
    dim3 gc(TILES, B);
    k_ce<<<gc, NT>>>(conf);
    k_topk<<<B, NT>>>();
    k_final<<<1, NT>>>((float*)d_out);
}

// round 6
// speedup vs baseline: 2.2744x; 2.2744x over previous
#include <cuda_runtime.h>
#include <math.h>

#define B 128
#define P 8732
#define O 16
#define C 21
#define NT 256
#define SB 4                       // sub-blocks per image for match kernel
#define PPB (P / SB)               // 2183 priors per sub-block
#define TILES ((P + NT - 1) / NT)  // 35
#define NTK 512                    // threads for top-k kernel
#define PPAD (18 * NTK)            // 9216: uniform trip count for warp-sync ops

// ---------------- device scratch (no allocations allowed) ----------------
__device__ unsigned short     g_tb  [B * P];       // tc | (bix<<8) per prior (pre-force)
__device__ unsigned long long g_part[B * SB * O];  // per-subblock per-truth packed argmax
__device__ float              g_negce[B * P];      // CE at negatives, 0 at positives
__device__ int                g_npt  [B * TILES];  // per-tile npos partials
__device__ float              g_loct [B * TILES];  // per-tile smoothL1 partials
__device__ float              g_posce[B * TILES];  // per-tile positive-CE partials
__device__ float              g_negsum[B];         // hard-negative top-K CE sum

__device__ __forceinline__ float sl1f(float x) {
    float ax = fabsf(x);
    return ax < 1.0f ? 0.5f * ax * ax : ax - 0.5f;
}

// ---------------- kernel 1: single-pass IoU -> per-prior best + per-truth partial argmax
__global__ __launch_bounds__(NT)
void k_match1(const float* __restrict__ boxes,
              const int*   __restrict__ labels,
              const float* __restrict__ priors) {
    const int b = blockIdx.y, s = blockIdx.x, tid = threadIdx.x;
    __shared__ float4 s_truth[O];
    __shared__ float  s_area[O];
    __shared__ int    s_label[O];
    __shared__ unsigned long long s_red[O * 8];

    if (tid < O) {
        float4 t = ((const float4*)boxes)[b * O + tid];
        s_truth[tid] = t;
        s_area[tid]  = (t.z - t.x) * (t.w - t.y);
        s_label[tid] = labels[b * O + tid];
    }
    __syncthreads();

    // per-truth best prior tracked as (value, index); thread scans ascending p
    // with strict > so first occurrence wins locally; reductions break ties by
    // smaller index (matches jnp.argmax).
    float tv[O]; int tp[O];
#pragma unroll
    for (int o = 0; o < O; o++) { tv[o] = -1.0f; tp[o] = 0; }

    const int p0 = s * PPB;
    for (int p = p0 + tid; p < p0 + PPB; p += NT) {
        float4 pr = ((const float4*)priors)[p];
        float px0 = pr.x - 0.5f * pr.z, py0 = pr.y - 0.5f * pr.w;
        float px1 = pr.x + 0.5f * pr.z, py1 = pr.y + 0.5f * pr.w;
        float pa  = pr.z * pr.w;
        float bov = -1.0f; int bix = 0;
#pragma unroll
        for (int o = 0; o < O; o++) {
            float4 t = s_truth[o];
            float ix = fmaxf(fminf(t.z, px1) - fmaxf(t.x, px0), 0.0f);
            float iy = fmaxf(fminf(t.w, py1) - fmaxf(t.y, py0), 0.0f);
            float inter = ix * iy;
            float iou = __fdividef(inter, s_area[o] + pa - inter);
            if (iou > bov) { bov = iou; bix = o; }     // ascending o: first occurrence
            if (iou > tv[o]) { tv[o] = iou; tp[o] = p; }
        }
        int tc = (bov < 0.5f) ? 0 : (s_label[bix] + 1);
        g_tb[b * P + p] = (unsigned short)(tc | (bix << 8));
    }

    const int lane = tid & 31, wid = tid >> 5;
#pragma unroll
    for (int o = 0; o < O; o++) {
        float v = tv[o]; int i = tp[o];
        for (int sh = 16; sh > 0; sh >>= 1) {
            float v2 = __shfl_down_sync(0xffffffffu, v, sh);
            int   i2 = __shfl_down_sync(0xffffffffu, i, sh);
            if (v2 > v || (v2 == v && i2 < i)) { v = v2; i = i2; }
        }
        if (lane == 0)
            s_red[o * 8 + wid] = ((unsigned long long)__float_as_uint(fmaxf(v, 0.0f)) << 32)
                               | (unsigned)(P - 1 - i);
    }
    __syncthreads();
    if (tid < O) {
        // packed (iou_bits<<32)|(P-1-p): max picks larger iou, then smaller p
        unsigned long long v = s_red[tid * 8];
        for (int w = 1; w < 8; w++) {
            unsigned long long v2 = s_red[tid * 8 + w];
            if (v2 > v) v = v2;
        }
        g_part[(b * SB + s) * O + tid] = v;
    }
}

// ---------------- kernel 2 (fused): forced-assign + conf + CE + loc loss ----------------
__global__ __launch_bounds__(NT)
void k_ce(const float* __restrict__ conf,
          const float* __restrict__ loc,
          const float* __restrict__ boxes,
          const int*   __restrict__ labels,
          const float* __restrict__ priors) {
    __shared__ float  s[NT * C];   // 21504 B
    __shared__ float4 s_truth[O];
    __shared__ int    s_label[O];
    __shared__ int    s_forced[O];
    __shared__ float  s_rp[8], s_rl[8];
    __shared__ int    s_rn[8];
    const int b = blockIdx.y, tile = blockIdx.x, tid = threadIdx.x;
    const int p0  = tile * NT;
    const int cnt = min(NT, P - p0);

    if (tid < O) {
        s_truth[tid] = ((const float4*)boxes)[b * O + tid];
        s_label[tid] = labels[b * O + tid];
        unsigned long long v = g_part[(b * SB + 0) * O + tid];
        for (int ss = 1; ss < SB; ss++) {
            unsigned long long v2 = g_part[(b * SB + ss) * O + tid];
            if (v2 > v) v = v2;
        }
        s_forced[tid] = P - 1 - (int)(unsigned)(v & 0xffffffffu);
    }

    // stage conf_preds: cnt*C divisible by 4 (256*21=5376, 28*21=588); base 16B aligned.
    const float4* src = (const float4*)(conf + ((size_t)b * P + p0) * C);
    float4* dst = (float4*)s;
    const int n4 = cnt * C / 4;
#pragma unroll 4
    for (int i = tid; i < n4; i += NT) dst[i] = src[i];
    __syncthreads();

    float posce = 0.0f, slsum = 0.0f; int npos = 0;
    if (tid < cnt) {
        const int p = p0 + tid;
        int tbv = g_tb[b * P + p];
        int tc  = tbv & 0xff;
        int bix = tbv >> 8;
#pragma unroll
        for (int o = 0; o < O; o++)                // ascending: last wins (matches .at.set)
            if (s_forced[o] == p) { bix = o; tc = s_label[o] + 1; }

        const float* x = s + tid * C;   // stride 21: bank-conflict-free
        float m = x[0];
#pragma unroll
        for (int c = 1; c < C; c++) m = fmaxf(m, x[c]);
        float sum = 0.0f;
#pragma unroll
        for (int c = 0; c < C; c++) sum += __expf(x[c] - m);
        float lse = m + __logf(sum);
        float ce = fmaxf(lse - x[tc], 0.0f);   // clamp: keep uint-order invariant

        if (tc > 0) {
            g_negce[b * P + p] = 0.0f;
            posce = ce;
            npos  = 1;
            float4 pr = ((const float4*)priors)[p];
            float4 t  = s_truth[bix];
            float4 lp = ((const float4*)loc)[b * P + p];
            float gx = __fdividef((t.x + t.z) * 0.5f - pr.x, 0.1f * pr.z);
            float gy = __fdividef((t.y + t.w) * 0.5f - pr.y, 0.1f * pr.w);
            float gw = __logf(__fdividef(t.z - t.x, pr.z)) * 5.0f;
            float gh = __logf(__fdividef(t.w - t.y, pr.w)) * 5.0f;
            slsum = sl1f(lp.x - gx) + sl1f(lp.y - gy)
                  + sl1f(lp.z - gw) + sl1f(lp.w - gh);
        } else {
            g_negce[b * P + p] = ce;
        }
    }
    float vp = posce, vl = slsum; int vn = npos;
    for (int s2 = 16; s2 > 0; s2 >>= 1) {
        vp += __shfl_down_sync(0xffffffffu, vp, s2);
        vl += __shfl_down_sync(0xffffffffu, vl, s2);
        vn += __shfl_down_sync(0xffffffffu, vn, s2);
    }
    if ((tid & 31) == 0) { int w = tid >> 5; s_rp[w] = vp; s_rl[w] = vl; s_rn[w] = vn; }
    __syncthreads();
    if (tid == 0) {
        float tpc = 0.0f, tlc = 0.0f; int tnc = 0;
        for (int w = 0; w < 8; w++) { tpc += s_rp[w]; tlc += s_rl[w]; tnc += s_rn[w]; }
        g_posce[b * TILES + tile] = tpc;
        g_loct [b * TILES + tile] = tlc;
        g_npt  [b * TILES + tile] = tnc;
    }
}

// ---------------- kernel 3: exact top-K sum via radix select in shared ----------------
__global__ __launch_bounds__(NTK)
void k_topk() {
    __shared__ float        sv[P];          // 34928 B
    __shared__ unsigned int hist[256];
    __shared__ unsigned int suf[257];       // suffix sums; suf[256] = 0
    __shared__ unsigned int s_sel, s_krem;
    __shared__ int          s_K;
    __shared__ float        s_s[NTK / 32];
    __shared__ unsigned int s_c[NTK / 32];
    const int b = blockIdx.x, tid = threadIdx.x;
    const int lane = tid & 31;

    if (tid == 0) s_K = 0;
    __syncthreads();
    const float4* src = (const float4*)(g_negce + b * P);   // P/4 = 2183
    float4* d4 = (float4*)sv;
    for (int i = tid; i < P / 4; i += NTK) d4[i] = src[i];
    if (tid < TILES) atomicAdd(&s_K, g_npt[b * TILES + tid]);
    __syncthreads();
    int K = 3 * s_K; if (K > P) K = P;
    if (K <= 0) { if (tid == 0) g_negsum[b] = 0.0f; return; }

    // CE >= 0 => float order == uint order. Radix-select K-th largest bit pattern.
    unsigned prefix = 0, prefmask = 0, Krem = (unsigned)K;
    for (int shift = 24; shift >= 0; shift -= 8) {
        if (tid < 256) hist[tid] = 0;
        __syncthreads();

        // histogram with warp-aggregated atomics (uniform trip count: PPAD % NTK == 0)
        for (int i = tid; i < PPAD; i += NTK) {
            unsigned key = 256u;   // sentinel: no contribution
            if (i < P) {
                unsigned u = __float_as_uint(sv[i]);
                if ((u & prefmask) == prefix) key = (u >> shift) & 255u;
            }
            unsigned grp = __match_any_sync(0xffffffffu, key);
            int leader = __ffs(grp) - 1;
            if (lane == leader && key != 256u)
                atomicAdd(&hist[key], (unsigned)__popc(grp));
        }
        __syncthreads();

        // suffix scan over 256 bins: warp 0 only, 8 bins per lane, 1 barrier
        if (tid < 32) {
            unsigned loc[8]; unsigned tot = 0;
#pragma unroll
            for (int k = 0; k < 8; k++) { loc[k] = hist[tid * 8 + k]; tot += loc[k]; }
            // inclusive suffix across lanes (sum of tot for lanes >= tid)
            unsigned run = tot;
#pragma unroll
            for (int off = 1; off < 32; off <<= 1) {
                unsigned v2 = __shfl_down_sync(0xffffffffu, run, off);
                if (tid + off < 32) run += v2;
            }
            unsigned acc = run - tot;   // sum over lanes > tid
#pragma unroll
            for (int k = 7; k >= 0; k--) { acc += loc[k]; suf[tid * 8 + k] = acc; }
            if (tid == 31) suf[256] = 0u;
        }
        __syncthreads();
        // unique bin with suffix_incl >= Krem and suffix_excl < Krem
        if (tid < 256) {
            unsigned incl = suf[tid], excl = suf[tid + 1];
            if (incl >= Krem && excl < Krem) {
                s_sel  = prefix | ((unsigned)tid << shift);
                s_krem = Krem - excl;
            }
        }
        __syncthreads();
        prefix = s_sel; Krem = s_krem;
        prefmask |= 0xFFu << shift;
        __syncthreads();
    }

    const float thr = __uint_as_float(prefix);   // exact K-th largest value
    float ssum = 0.0f; unsigned cgt = 0;
    for (int i = tid; i < P; i += NTK) {
        float v = sv[i];
        if (v > thr) { ssum += v; cgt++; }
    }
    for (int s = 16; s > 0; s >>= 1) {
        ssum += __shfl_down_sync(0xffffffffu, ssum, s);
        cgt  += __shfl_down_sync(0xffffffffu, cgt, s);
    }
    if (lane == 0) { s_s[tid >> 5] = ssum; s_c[tid >> 5] = cgt; }
    __syncthreads();
    if (tid == 0) {
        float ts = 0.0f; unsigned tc = 0;
        for (int w = 0; w < NTK / 32; w++) { ts += s_s[w]; tc += s_c[w]; }
        g_negsum[b] = ts + (float)((unsigned)K - tc) * thr;  // exact tie handling
    }
}

// ---------------- kernel 4: final scalar ----------------
__global__ __launch_bounds__(NT)
void k_final(float* __restrict__ out) {
    __shared__ float s_l[8], s_p[8], s_n[8];
    __shared__ int   s_c[8];
    const int tid = threadIdx.x;
    float locs = 0.0f, poss = 0.0f, negs = 0.0f; int np = 0;
    for (int i = tid; i < B * TILES; i += NT) {
        locs += g_loct[i]; poss += g_posce[i]; np += g_npt[i];
    }
    for (int b = tid; b < B; b += NT) negs += g_negsum[b];
    for (int s = 16; s > 0; s >>= 1) {
        locs += __shfl_down_sync(0xffffffffu, locs, s);
        poss += __shfl_down_sync(0xffffffffu, poss, s);
        negs += __shfl_down_sync(0xffffffffu, negs, s);
        np   += __shfl_down_sync(0xffffffffu, np, s);
    }
    if ((tid & 31) == 0) {
        int w = tid >> 5;
        s_l[w] = locs; s_p[w] = poss; s_n[w] = negs; s_c[w] = np;
    }
    __syncthreads();
    if (tid == 0) {
        float tl = 0, tp = 0, tn = 0; int tc = 0;
        for (int w = 0; w < 8; w++) { tl += s_l[w]; tp += s_p[w]; tn += s_n[w]; tc += s_c[w]; }
        float npf = (float)tc;
        out[0] = (tn + tp) / (npf + 1e-7f) + tl / (4.0f * npf);
    }
}

// ---------------- launcher ----------------
extern "C" void kernel_launch(void* const* d_in, const int* in_sizes, int n_in,
                              void* d_out, int out_size) {
    (void)in_sizes; (void)n_in; (void)out_size;
    const float* loc    = (const float*)d_in[0];
    const float* conf   = (const float*)d_in[1];
    const float* boxes  = (const float*)d_in[2];
    const int*   labels = (const int*)  d_in[3];
    const float* priors = (const float*)d_in[4];

    dim3 gm(SB, B);
    k_match1<<<gm, NT>>>(boxes, labels, priors);
    dim3 gc(TILES, B);
    k_ce<<<gc, NT>>>(conf, loc, boxes, labels, priors);
    k_topk<<<B, NTK>>>();
    k_final<<<1, NT>>>((float*)d_out);
}